// round 2
// baseline (speedup 1.0000x reference)
#include <cuda_runtime.h>

// Problem constants (fixed by the dataset)
#define T_LEN   262144
#define B_N     16
#define W_LEN   8640
#define PAD     4320            // W_LEN/2
#define F_META  8
#define XPAD_LEN (T_LEN + W_LEN)   // 270784, %4==0 so float4-aligned rows

#define TILE      1024
#define CTHREADS  256
#define NCHUNK    32            // reduction chunks per batch

// Device scratch (static allocations only — no cudaMalloc allowed)
__device__ float g_w[W_LEN];                 // flipped softmax kernel: c[i] = softmax(tw)[W-1-i]
__device__ float g_xpad[B_N * XPAD_LEN];     // edge-padded attenuation (17.3 MB)
__device__ float g_partial[B_N * NCHUNK];
__device__ float g_scale[B_N];               // (1 + correction_scale * tanh(...))

// ---------------------------------------------------------------------------
// K0a: softmax over temporal_weights (8640), store flipped into g_w
// ---------------------------------------------------------------------------
__global__ void softmax_flip_kernel(const float* __restrict__ tw) {
    __shared__ float red[256];
    __shared__ float s_max, s_invsum;
    const int tid = threadIdx.x;

    float m = -1e30f;
    for (int i = tid; i < W_LEN; i += 256) m = fmaxf(m, tw[i]);
    red[tid] = m; __syncthreads();
    for (int s = 128; s > 0; s >>= 1) {
        if (tid < s) red[tid] = fmaxf(red[tid], red[tid + s]);
        __syncthreads();
    }
    if (tid == 0) s_max = red[0];
    __syncthreads();
    const float mx = s_max;
    __syncthreads();   // protect red[] reuse

    float sum = 0.f;
    for (int i = tid; i < W_LEN; i += 256) sum += expf(tw[i] - mx);
    red[tid] = sum; __syncthreads();
    for (int s = 128; s > 0; s >>= 1) {
        if (tid < s) red[tid] += red[tid + s];
        __syncthreads();
    }
    if (tid == 0) s_invsum = 1.f / red[0];
    __syncthreads();
    const float inv = s_invsum;

    for (int i = tid; i < W_LEN; i += 256)
        g_w[W_LEN - 1 - i] = expf(tw[i] - mx) * inv;
}

// ---------------------------------------------------------------------------
// K0b: build edge-padded input:  g_xpad[b][u] = att[b][clamp(u-PAD, 0, T-1)]
// ---------------------------------------------------------------------------
__global__ void pad_kernel(const float* __restrict__ att) {
    int idx = blockIdx.x * blockDim.x + threadIdx.x;
    if (idx < B_N * XPAD_LEN) {
        int b = idx / XPAD_LEN;
        int u = idx - b * XPAD_LEN;
        int t = u - PAD;
        t = min(max(t, 0), T_LEN - 1);
        g_xpad[idx] = att[b * T_LEN + t];
    }
}

// ---------------------------------------------------------------------------
// K1: FIR conv.  baseline[b][t] = sum_i g_w[i] * g_xpad[b][t + i]
// Each thread produces 4 consecutive outputs with a sliding float4:
// per 4 taps: 1x LDS.128 input (conflict-free), 1x LDS.128 weight (broadcast),
// 16 FFMAs -> FMA-pipe-bound.
// ---------------------------------------------------------------------------
__global__ void __launch_bounds__(CTHREADS) conv_kernel(float* __restrict__ out) {
    extern __shared__ float smem[];
    float* ws = smem;                  // W_LEN floats
    float* xs = smem + W_LEN;          // TILE + W_LEN floats (needs TILE+W_LEN-1+1)

    const int b  = blockIdx.y;
    const int t0 = blockIdx.x * TILE;

    // stage weights
    {
        const float4* gw4 = (const float4*)g_w;
        float4* ws4 = (float4*)ws;
        for (int i = threadIdx.x; i < W_LEN / 4; i += CTHREADS) ws4[i] = gw4[i];
    }
    // stage input tile (TILE + W_LEN floats)
    {
        const float4* gx4 = (const float4*)(g_xpad + b * XPAD_LEN + t0);
        float4* xs4 = (float4*)xs;
        for (int i = threadIdx.x; i < (TILE + W_LEN) / 4; i += CTHREADS) xs4[i] = gx4[i];
    }
    __syncthreads();

    const float4* xs4 = (const float4*)(xs + threadIdx.x * 4);  // 16B-aligned
    const float4* ws4 = (const float4*)ws;

    float4 acc = make_float4(0.f, 0.f, 0.f, 0.f);
    float4 x0 = xs4[0];

#pragma unroll 4
    for (int kk = 0; kk < W_LEN / 4; ++kk) {
        const float4 wv = ws4[kk];
        const float4 x1 = xs4[kk + 1];
        // j = 0 : taps 4kk+0
        acc.x = fmaf(wv.x, x0.x, acc.x);
        acc.y = fmaf(wv.x, x0.y, acc.y);
        acc.z = fmaf(wv.x, x0.z, acc.z);
        acc.w = fmaf(wv.x, x0.w, acc.w);
        // j = 1
        acc.x = fmaf(wv.y, x0.y, acc.x);
        acc.y = fmaf(wv.y, x0.z, acc.y);
        acc.z = fmaf(wv.y, x0.w, acc.z);
        acc.w = fmaf(wv.y, x1.x, acc.w);
        // j = 2
        acc.x = fmaf(wv.z, x0.z, acc.x);
        acc.y = fmaf(wv.z, x0.w, acc.y);
        acc.z = fmaf(wv.z, x1.x, acc.z);
        acc.w = fmaf(wv.z, x1.y, acc.w);
        // j = 3
        acc.x = fmaf(wv.w, x0.w, acc.x);
        acc.y = fmaf(wv.w, x1.x, acc.y);
        acc.z = fmaf(wv.w, x1.y, acc.z);
        acc.w = fmaf(wv.w, x1.z, acc.w);
        x0 = x1;
    }

    ((float4*)(out + b * T_LEN + t0))[threadIdx.x] = acc;
}

// ---------------------------------------------------------------------------
// K2: per-(batch,chunk) partial sums of baseline (for the mean)
// ---------------------------------------------------------------------------
__global__ void reduce_kernel(const float* __restrict__ base) {
    __shared__ float red[256];
    const int b = blockIdx.y, c = blockIdx.x;
    const int chunk = T_LEN / NCHUNK;            // 8192
    const float4* p = (const float4*)(base + b * T_LEN + c * chunk);
    float s = 0.f;
    for (int i = threadIdx.x; i < chunk / 4; i += 256) {
        float4 v = p[i];
        s += (v.x + v.y) + (v.z + v.w);
    }
    red[threadIdx.x] = s; __syncthreads();
    for (int st = 128; st > 0; st >>= 1) {
        if (threadIdx.x < st) red[threadIdx.x] += red[threadIdx.x + st];
        __syncthreads();
    }
    if (threadIdx.x == 0) g_partial[b * NCHUNK + c] = red[0];
}

// ---------------------------------------------------------------------------
// K3: tiny MLP per batch -> g_scale[b] = 1 + cs * tanh(MLP([mean, meta]))
// ---------------------------------------------------------------------------
__global__ void mlp_kernel(const float* __restrict__ meta,
                           const float* __restrict__ W1, const float* __restrict__ b1,
                           const float* __restrict__ W2, const float* __restrict__ b2,
                           const float* __restrict__ W3, const float* __restrict__ b3,
                           const float* __restrict__ cs) {
    const int b = threadIdx.x;
    if (b >= B_N) return;
    float s = 0.f;
    for (int i = 0; i < NCHUNK; ++i) s += g_partial[b * NCHUNK + i];

    float ci[1 + F_META];
    ci[0] = s / (float)T_LEN;
    for (int i = 0; i < F_META; ++i) ci[1 + i] = meta[b * F_META + i];

    float h1[32];
    for (int j = 0; j < 32; ++j) {
        float a = b1[j];
        for (int i = 0; i < 1 + F_META; ++i) a = fmaf(W1[j * (1 + F_META) + i], ci[i], a);
        h1[j] = fmaxf(a, 0.f);
    }
    float h2[16];
    for (int j = 0; j < 16; ++j) {
        float a = b2[j];
        for (int i = 0; i < 32; ++i) a = fmaf(W2[j * 32 + i], h1[i], a);
        h2[j] = fmaxf(a, 0.f);
    }
    float f = b3[0];
    for (int i = 0; i < 16; ++i) f = fmaf(W3[i], h2[i], f);
    g_scale[b] = 1.f + cs[0] * tanhf(f);
}

// ---------------------------------------------------------------------------
// K4: in-place rescale of the baseline by (1 + correction)
// ---------------------------------------------------------------------------
__global__ void scale_kernel(float* __restrict__ out) {
    int idx = blockIdx.x * blockDim.x + threadIdx.x;   // over B*T/4 float4s
    const int per_b = T_LEN / 4;
    int b = idx / per_b;
    float s = g_scale[b];
    float4* o4 = (float4*)out;
    float4 v = o4[idx];
    v.x *= s; v.y *= s; v.z *= s; v.w *= s;
    o4[idx] = v;
}

// ---------------------------------------------------------------------------
// Launch
// ---------------------------------------------------------------------------
extern "C" void kernel_launch(void* const* d_in, const int* in_sizes, int n_in,
                              void* d_out, int out_size) {
    const float* att  = (const float*)d_in[0];   // (B,1,T)
    const float* meta = (const float*)d_in[1];   // (B,8)
    const float* tw   = (const float*)d_in[2];   // (8640,)
    const float* W1   = (const float*)d_in[3];
    const float* b1   = (const float*)d_in[4];
    const float* W2   = (const float*)d_in[5];
    const float* b2   = (const float*)d_in[6];
    const float* W3   = (const float*)d_in[7];
    const float* b3   = (const float*)d_in[8];
    const float* cs   = (const float*)d_in[9];
    float* out = (float*)d_out;

    const int smem_bytes = (W_LEN + TILE + W_LEN) * (int)sizeof(float);  // 73216
    cudaFuncSetAttribute(conv_kernel, cudaFuncAttributeMaxDynamicSharedMemorySize, smem_bytes);

    softmax_flip_kernel<<<1, 256>>>(tw);
    pad_kernel<<<(B_N * XPAD_LEN + 255) / 256, 256>>>(att);
    conv_kernel<<<dim3(T_LEN / TILE, B_N), CTHREADS, smem_bytes>>>(out);
    reduce_kernel<<<dim3(NCHUNK, B_N), 256>>>(out);
    mlp_kernel<<<1, 32>>>(meta, W1, b1, W2, b2, W3, b3, cs);
    scale_kernel<<<(B_N * T_LEN / 4 + 255) / 256, 256>>>(out);
}

// round 3
// speedup vs baseline: 1.7235x; 1.7235x over previous
#include <cuda_runtime.h>

// Problem constants (fixed by the dataset)
#define T_LEN   262144
#define B_N     16
#define W_LEN   8640
#define PAD     4320            // W_LEN/2
#define F_META  8
#define XPAD_LEN (T_LEN + W_LEN)   // 270784, %4==0 so float4-aligned rows

#define TILE      2048          // outputs per block (2 regions of 1024)
#define REGOFF    1024          // region-1 offset inside the tile
#define CTHREADS  256
#define NCHUNK    32            // reduction chunks per batch

// Device scratch (static allocations only — no cudaMalloc allowed)
__device__ float g_w[W_LEN];                 // flipped softmax kernel
__device__ float g_xpad[B_N * XPAD_LEN];     // edge-padded attenuation (17.3 MB)
__device__ float g_partial[B_N * NCHUNK];
__device__ float g_scale[B_N];

// ---------------------------------------------------------------------------
// Packed fp32x2 helpers (Blackwell FFMA2 path — PTX-only, ptxas won't auto-fuse)
// ---------------------------------------------------------------------------
__device__ __forceinline__ unsigned long long pack2(float lo, float hi) {
    unsigned long long r;
    asm("mov.b64 %0, {%1, %2};" : "=l"(r) : "f"(lo), "f"(hi));
    return r;
}
__device__ __forceinline__ void unpack2(unsigned long long v, float& lo, float& hi) {
    asm("mov.b64 {%0, %1}, %2;" : "=f"(lo), "=f"(hi) : "l"(v));
}
__device__ __forceinline__ void fma2(unsigned long long& acc,
                                     unsigned long long a, unsigned long long b) {
    asm("fma.rn.f32x2 %0, %1, %2, %0;" : "+l"(acc) : "l"(a), "l"(b));
}

// ---------------------------------------------------------------------------
// K0a: softmax over temporal_weights (8640), store flipped into g_w
// ---------------------------------------------------------------------------
__global__ void softmax_flip_kernel(const float* __restrict__ tw) {
    __shared__ float red[256];
    __shared__ float s_max, s_invsum;
    const int tid = threadIdx.x;

    float m = -1e30f;
    for (int i = tid; i < W_LEN; i += 256) m = fmaxf(m, tw[i]);
    red[tid] = m; __syncthreads();
    for (int s = 128; s > 0; s >>= 1) {
        if (tid < s) red[tid] = fmaxf(red[tid], red[tid + s]);
        __syncthreads();
    }
    if (tid == 0) s_max = red[0];
    __syncthreads();
    const float mx = s_max;
    __syncthreads();

    float sum = 0.f;
    for (int i = tid; i < W_LEN; i += 256) sum += expf(tw[i] - mx);
    red[tid] = sum; __syncthreads();
    for (int s = 128; s > 0; s >>= 1) {
        if (tid < s) red[tid] += red[tid + s];
        __syncthreads();
    }
    if (tid == 0) s_invsum = 1.f / red[0];
    __syncthreads();
    const float inv = s_invsum;

    for (int i = tid; i < W_LEN; i += 256)
        g_w[W_LEN - 1 - i] = expf(tw[i] - mx) * inv;
}

// ---------------------------------------------------------------------------
// K0b: edge-padded input:  g_xpad[b][u] = att[b][clamp(u-PAD, 0, T-1)]
// ---------------------------------------------------------------------------
__global__ void pad_kernel(const float* __restrict__ att) {
    int idx = blockIdx.x * blockDim.x + threadIdx.x;
    if (idx < B_N * XPAD_LEN) {
        int b = idx / XPAD_LEN;
        int u = idx - b * XPAD_LEN;
        int t = u - PAD;
        t = min(max(t, 0), T_LEN - 1);
        g_xpad[idx] = att[b * T_LEN + t];
    }
}

// ---------------------------------------------------------------------------
// K1: FIR conv with packed f32x2 FMAs.
// Each thread produces 8 outputs: 4 at region0 (4*tid) and 4 at region1
// (REGOFF + 4*tid). Both regions are 16B-stride across lanes -> conflict-free
// LDS.128. Per 4 taps: 16 FFMA2 (= 64 lane-FMAs) + 2 input LDS.128 + 1 weight
// broadcast LDS.128 + ~12 pack MOVs.
// ---------------------------------------------------------------------------
__global__ void __launch_bounds__(CTHREADS) conv_kernel(float* __restrict__ out) {
    extern __shared__ float smem[];
    float* ws = smem;                  // W_LEN floats
    float* xs = smem + W_LEN;          // TILE + W_LEN floats

    const int b  = blockIdx.y;
    const int t0 = blockIdx.x * TILE;

    // stage weights
    {
        const float4* gw4 = (const float4*)g_w;
        float4* ws4 = (float4*)ws;
        for (int i = threadIdx.x; i < W_LEN / 4; i += CTHREADS) ws4[i] = gw4[i];
    }
    // stage input tile (TILE + W_LEN floats)
    {
        const float4* gx4 = (const float4*)(g_xpad + b * XPAD_LEN + t0);
        float4* xs4 = (float4*)xs;
        for (int i = threadIdx.x; i < (TILE + W_LEN) / 4; i += CTHREADS) xs4[i] = gx4[i];
    }
    __syncthreads();

    const float4* p0 = (const float4*)(xs + threadIdx.x * 4);           // region 0
    const float4* p1 = (const float4*)(xs + REGOFF + threadIdx.x * 4);  // region 1
    const float4* ws4 = (const float4*)ws;

    unsigned long long a01_0 = pack2(0.f, 0.f), a23_0 = pack2(0.f, 0.f);
    unsigned long long a01_1 = pack2(0.f, 0.f), a23_1 = pack2(0.f, 0.f);

    float4 xa0 = p0[0];
    float4 xa1 = p1[0];

#pragma unroll 2
    for (int kk = 0; kk < W_LEN / 4; ++kk) {
        const float4 wv  = ws4[kk];
        const float4 xb0 = p0[kk + 1];
        const float4 xb1 = p1[kk + 1];

        const unsigned long long wp0 = pack2(wv.x, wv.x);
        const unsigned long long wp1 = pack2(wv.y, wv.y);
        const unsigned long long wp2 = pack2(wv.z, wv.z);
        const unsigned long long wp3 = pack2(wv.w, wv.w);

        // ---- region 0 ----
        {
            const unsigned long long e0 = pack2(xa0.x, xa0.y);
            const unsigned long long e1 = pack2(xa0.z, xa0.w);
            const unsigned long long e2 = pack2(xb0.x, xb0.y);
            const unsigned long long e3 = pack2(xb0.z, xb0.w);
            const unsigned long long o0 = pack2(xa0.y, xa0.z);
            const unsigned long long o1 = pack2(xa0.w, xb0.x);
            const unsigned long long o2 = pack2(xb0.y, xb0.z);
            fma2(a01_0, wp0, e0); fma2(a23_0, wp0, e1);
            fma2(a01_0, wp1, o0); fma2(a23_0, wp1, o1);
            fma2(a01_0, wp2, e1); fma2(a23_0, wp2, e2);
            fma2(a01_0, wp3, o1); fma2(a23_0, wp3, o2);
            (void)e3;
        }
        // ---- region 1 ----
        {
            const unsigned long long e0 = pack2(xa1.x, xa1.y);
            const unsigned long long e1 = pack2(xa1.z, xa1.w);
            const unsigned long long e2 = pack2(xb1.x, xb1.y);
            const unsigned long long e3 = pack2(xb1.z, xb1.w);
            const unsigned long long o0 = pack2(xa1.y, xa1.z);
            const unsigned long long o1 = pack2(xa1.w, xb1.x);
            const unsigned long long o2 = pack2(xb1.y, xb1.z);
            fma2(a01_1, wp0, e0); fma2(a23_1, wp0, e1);
            fma2(a01_1, wp1, o0); fma2(a23_1, wp1, o1);
            fma2(a01_1, wp2, e1); fma2(a23_1, wp2, e2);
            fma2(a01_1, wp3, o1); fma2(a23_1, wp3, o2);
            (void)e3;
        }
        xa0 = xb0;
        xa1 = xb1;
    }

    float o0, o1, o2, o3;
    unpack2(a01_0, o0, o1); unpack2(a23_0, o2, o3);
    ((float4*)(out + b * T_LEN + t0))[threadIdx.x] = make_float4(o0, o1, o2, o3);
    unpack2(a01_1, o0, o1); unpack2(a23_1, o2, o3);
    ((float4*)(out + b * T_LEN + t0 + REGOFF))[threadIdx.x] = make_float4(o0, o1, o2, o3);
}

// ---------------------------------------------------------------------------
// K2: per-(batch,chunk) partial sums of baseline (for the mean)
// ---------------------------------------------------------------------------
__global__ void reduce_kernel(const float* __restrict__ base) {
    __shared__ float red[256];
    const int b = blockIdx.y, c = blockIdx.x;
    const int chunk = T_LEN / NCHUNK;            // 8192
    const float4* p = (const float4*)(base + b * T_LEN + c * chunk);
    float s = 0.f;
    for (int i = threadIdx.x; i < chunk / 4; i += 256) {
        float4 v = p[i];
        s += (v.x + v.y) + (v.z + v.w);
    }
    red[threadIdx.x] = s; __syncthreads();
    for (int st = 128; st > 0; st >>= 1) {
        if (threadIdx.x < st) red[threadIdx.x] += red[threadIdx.x + st];
        __syncthreads();
    }
    if (threadIdx.x == 0) g_partial[b * NCHUNK + c] = red[0];
}

// ---------------------------------------------------------------------------
// K3: tiny MLP per batch -> g_scale[b] = 1 + cs * tanh(MLP([mean, meta]))
// ---------------------------------------------------------------------------
__global__ void mlp_kernel(const float* __restrict__ meta,
                           const float* __restrict__ W1, const float* __restrict__ b1,
                           const float* __restrict__ W2, const float* __restrict__ b2,
                           const float* __restrict__ W3, const float* __restrict__ b3,
                           const float* __restrict__ cs) {
    const int b = threadIdx.x;
    if (b >= B_N) return;
    float s = 0.f;
    for (int i = 0; i < NCHUNK; ++i) s += g_partial[b * NCHUNK + i];

    float ci[1 + F_META];
    ci[0] = s / (float)T_LEN;
    for (int i = 0; i < F_META; ++i) ci[1 + i] = meta[b * F_META + i];

    float h1[32];
    for (int j = 0; j < 32; ++j) {
        float a = b1[j];
        for (int i = 0; i < 1 + F_META; ++i) a = fmaf(W1[j * (1 + F_META) + i], ci[i], a);
        h1[j] = fmaxf(a, 0.f);
    }
    float h2[16];
    for (int j = 0; j < 16; ++j) {
        float a = b2[j];
        for (int i = 0; i < 32; ++i) a = fmaf(W2[j * 32 + i], h1[i], a);
        h2[j] = fmaxf(a, 0.f);
    }
    float f = b3[0];
    for (int i = 0; i < 16; ++i) f = fmaf(W3[i], h2[i], f);
    g_scale[b] = 1.f + cs[0] * tanhf(f);
}

// ---------------------------------------------------------------------------
// K4: in-place rescale of the baseline by (1 + correction)
// ---------------------------------------------------------------------------
__global__ void scale_kernel(float* __restrict__ out) {
    int idx = blockIdx.x * blockDim.x + threadIdx.x;   // over B*T/4 float4s
    const int per_b = T_LEN / 4;
    int b = idx / per_b;
    float s = g_scale[b];
    float4* o4 = (float4*)out;
    float4 v = o4[idx];
    v.x *= s; v.y *= s; v.z *= s; v.w *= s;
    o4[idx] = v;
}

// ---------------------------------------------------------------------------
// Launch
// ---------------------------------------------------------------------------
extern "C" void kernel_launch(void* const* d_in, const int* in_sizes, int n_in,
                              void* d_out, int out_size) {
    const float* att  = (const float*)d_in[0];   // (B,1,T)
    const float* meta = (const float*)d_in[1];   // (B,8)
    const float* tw   = (const float*)d_in[2];   // (8640,)
    const float* W1   = (const float*)d_in[3];
    const float* b1   = (const float*)d_in[4];
    const float* W2   = (const float*)d_in[5];
    const float* b2   = (const float*)d_in[6];
    const float* W3   = (const float*)d_in[7];
    const float* b3   = (const float*)d_in[8];
    const float* cs   = (const float*)d_in[9];
    float* out = (float*)d_out;

    const int smem_bytes = (W_LEN + TILE + W_LEN) * (int)sizeof(float);  // 77312
    cudaFuncSetAttribute(conv_kernel, cudaFuncAttributeMaxDynamicSharedMemorySize, smem_bytes);

    softmax_flip_kernel<<<1, 256>>>(tw);
    pad_kernel<<<(B_N * XPAD_LEN + 255) / 256, 256>>>(att);
    conv_kernel<<<dim3(T_LEN / TILE, B_N), CTHREADS, smem_bytes>>>(out);
    reduce_kernel<<<dim3(NCHUNK, B_N), 256>>>(out);
    mlp_kernel<<<1, 32>>>(meta, W1, b1, W2, b2, W3, b3, cs);
    scale_kernel<<<(B_N * T_LEN / 4 + 255) / 256, 256>>>(out);
}

// round 6
// speedup vs baseline: 1.7240x; 1.0003x over previous
#include <cuda_runtime.h>

// Problem constants (fixed by the dataset)
#define T_LEN   262144
#define B_N     16
#define W_LEN   8640
#define PAD     4320            // W_LEN/2
#define F_META  8
#define XPAD_LEN (T_LEN + W_LEN)   // 270784, %4==0 so float4-aligned rows

#define TILE      2048          // outputs per block (2 regions of 1024)
#define REGOFF    1024          // region-1 offset inside the tile
#define CTHREADS  256
#define NCHUNK    32            // reduction chunks per batch

// Device scratch (static allocations only — no cudaMalloc allowed)
__device__ float g_w[W_LEN];                 // flipped softmax kernel
__device__ float g_xpad[B_N * XPAD_LEN];     // edge-padded attenuation (17.3 MB)
__device__ float g_partial[B_N * NCHUNK];
__device__ float g_scale[B_N];

// ---------------------------------------------------------------------------
// Packed fp32x2 helpers (Blackwell FFMA2 path — PTX-only, ptxas won't auto-fuse)
// ---------------------------------------------------------------------------
__device__ __forceinline__ unsigned long long pack2(float lo, float hi) {
    unsigned long long r;
    asm("mov.b64 %0, {%1, %2};" : "=l"(r) : "f"(lo), "f"(hi));
    return r;
}
__device__ __forceinline__ void unpack2(unsigned long long v, float& lo, float& hi) {
    asm("mov.b64 {%0, %1}, %2;" : "=f"(lo), "=f"(hi) : "l"(v));
}
__device__ __forceinline__ void fma2(unsigned long long& acc,
                                     unsigned long long a, unsigned long long b) {
    asm("fma.rn.f32x2 %0, %1, %2, %0;" : "+l"(acc) : "l"(a), "l"(b));
}

// ---------------------------------------------------------------------------
// K0a: softmax over temporal_weights (8640), store flipped into g_w
// ---------------------------------------------------------------------------
__global__ void softmax_flip_kernel(const float* __restrict__ tw) {
    __shared__ float red[256];
    __shared__ float s_max, s_invsum;
    const int tid = threadIdx.x;

    float m = -1e30f;
    for (int i = tid; i < W_LEN; i += 256) m = fmaxf(m, tw[i]);
    red[tid] = m; __syncthreads();
    for (int s = 128; s > 0; s >>= 1) {
        if (tid < s) red[tid] = fmaxf(red[tid], red[tid + s]);
        __syncthreads();
    }
    if (tid == 0) s_max = red[0];
    __syncthreads();
    const float mx = s_max;
    __syncthreads();

    float sum = 0.f;
    for (int i = tid; i < W_LEN; i += 256) sum += expf(tw[i] - mx);
    red[tid] = sum; __syncthreads();
    for (int s = 128; s > 0; s >>= 1) {
        if (tid < s) red[tid] += red[tid + s];
        __syncthreads();
    }
    if (tid == 0) s_invsum = 1.f / red[0];
    __syncthreads();
    const float inv = s_invsum;

    for (int i = tid; i < W_LEN; i += 256)
        g_w[W_LEN - 1 - i] = expf(tw[i] - mx) * inv;
}

// ---------------------------------------------------------------------------
// K0b: edge-padded input:  g_xpad[b][u] = att[b][clamp(u-PAD, 0, T-1)]
// ---------------------------------------------------------------------------
__global__ void pad_kernel(const float* __restrict__ att) {
    int idx = blockIdx.x * blockDim.x + threadIdx.x;
    if (idx < B_N * XPAD_LEN) {
        int b = idx / XPAD_LEN;
        int u = idx - b * XPAD_LEN;
        int t = u - PAD;
        t = min(max(t, 0), T_LEN - 1);
        g_xpad[idx] = att[b * T_LEN + t];
    }
}

// ---------------------------------------------------------------------------
// K1: FIR conv with packed f32x2 FMAs.
// Each thread produces 8 outputs: 4 at region0 (4*tid) and 4 at region1
// (REGOFF + 4*tid). Both regions are 16B-stride across lanes -> conflict-free
// LDS.128. Per 4 taps: 16 FFMA2 (= 64 lane-FMAs) + 2 input LDS.128 + 1 weight
// broadcast LDS.128 + ~12 pack MOVs.
// ---------------------------------------------------------------------------
__global__ void __launch_bounds__(CTHREADS) conv_kernel(float* __restrict__ out) {
    extern __shared__ float smem[];
    float* ws = smem;                  // W_LEN floats
    float* xs = smem + W_LEN;          // TILE + W_LEN floats

    const int b  = blockIdx.y;
    const int t0 = blockIdx.x * TILE;

    // stage weights
    {
        const float4* gw4 = (const float4*)g_w;
        float4* ws4 = (float4*)ws;
        for (int i = threadIdx.x; i < W_LEN / 4; i += CTHREADS) ws4[i] = gw4[i];
    }
    // stage input tile (TILE + W_LEN floats)
    {
        const float4* gx4 = (const float4*)(g_xpad + b * XPAD_LEN + t0);
        float4* xs4 = (float4*)xs;
        for (int i = threadIdx.x; i < (TILE + W_LEN) / 4; i += CTHREADS) xs4[i] = gx4[i];
    }
    __syncthreads();

    const float4* p0 = (const float4*)(xs + threadIdx.x * 4);           // region 0
    const float4* p1 = (const float4*)(xs + REGOFF + threadIdx.x * 4);  // region 1
    const float4* ws4 = (const float4*)ws;

    unsigned long long a01_0 = pack2(0.f, 0.f), a23_0 = pack2(0.f, 0.f);
    unsigned long long a01_1 = pack2(0.f, 0.f), a23_1 = pack2(0.f, 0.f);

    float4 xa0 = p0[0];
    float4 xa1 = p1[0];

#pragma unroll 2
    for (int kk = 0; kk < W_LEN / 4; ++kk) {
        const float4 wv  = ws4[kk];
        const float4 xb0 = p0[kk + 1];
        const float4 xb1 = p1[kk + 1];

        const unsigned long long wp0 = pack2(wv.x, wv.x);
        const unsigned long long wp1 = pack2(wv.y, wv.y);
        const unsigned long long wp2 = pack2(wv.z, wv.z);
        const unsigned long long wp3 = pack2(wv.w, wv.w);

        // ---- region 0 ----
        {
            const unsigned long long e0 = pack2(xa0.x, xa0.y);
            const unsigned long long e1 = pack2(xa0.z, xa0.w);
            const unsigned long long e2 = pack2(xb0.x, xb0.y);
            const unsigned long long e3 = pack2(xb0.z, xb0.w);
            const unsigned long long o0 = pack2(xa0.y, xa0.z);
            const unsigned long long o1 = pack2(xa0.w, xb0.x);
            const unsigned long long o2 = pack2(xb0.y, xb0.z);
            fma2(a01_0, wp0, e0); fma2(a23_0, wp0, e1);
            fma2(a01_0, wp1, o0); fma2(a23_0, wp1, o1);
            fma2(a01_0, wp2, e1); fma2(a23_0, wp2, e2);
            fma2(a01_0, wp3, o1); fma2(a23_0, wp3, o2);
            (void)e3;
        }
        // ---- region 1 ----
        {
            const unsigned long long e0 = pack2(xa1.x, xa1.y);
            const unsigned long long e1 = pack2(xa1.z, xa1.w);
            const unsigned long long e2 = pack2(xb1.x, xb1.y);
            const unsigned long long e3 = pack2(xb1.z, xb1.w);
            const unsigned long long o0 = pack2(xa1.y, xa1.z);
            const unsigned long long o1 = pack2(xa1.w, xb1.x);
            const unsigned long long o2 = pack2(xb1.y, xb1.z);
            fma2(a01_1, wp0, e0); fma2(a23_1, wp0, e1);
            fma2(a01_1, wp1, o0); fma2(a23_1, wp1, o1);
            fma2(a01_1, wp2, e1); fma2(a23_1, wp2, e2);
            fma2(a01_1, wp3, o1); fma2(a23_1, wp3, o2);
            (void)e3;
        }
        xa0 = xb0;
        xa1 = xb1;
    }

    float o0, o1, o2, o3;
    unpack2(a01_0, o0, o1); unpack2(a23_0, o2, o3);
    ((float4*)(out + b * T_LEN + t0))[threadIdx.x] = make_float4(o0, o1, o2, o3);
    unpack2(a01_1, o0, o1); unpack2(a23_1, o2, o3);
    ((float4*)(out + b * T_LEN + t0 + REGOFF))[threadIdx.x] = make_float4(o0, o1, o2, o3);
}

// ---------------------------------------------------------------------------
// K2: per-(batch,chunk) partial sums of baseline (for the mean)
// ---------------------------------------------------------------------------
__global__ void reduce_kernel(const float* __restrict__ base) {
    __shared__ float red[256];
    const int b = blockIdx.y, c = blockIdx.x;
    const int chunk = T_LEN / NCHUNK;            // 8192
    const float4* p = (const float4*)(base + b * T_LEN + c * chunk);
    float s = 0.f;
    for (int i = threadIdx.x; i < chunk / 4; i += 256) {
        float4 v = p[i];
        s += (v.x + v.y) + (v.z + v.w);
    }
    red[threadIdx.x] = s; __syncthreads();
    for (int st = 128; st > 0; st >>= 1) {
        if (threadIdx.x < st) red[threadIdx.x] += red[threadIdx.x + st];
        __syncthreads();
    }
    if (threadIdx.x == 0) g_partial[b * NCHUNK + c] = red[0];
}

// ---------------------------------------------------------------------------
// K3: tiny MLP per batch -> g_scale[b] = 1 + cs * tanh(MLP([mean, meta]))
// ---------------------------------------------------------------------------
__global__ void mlp_kernel(const float* __restrict__ meta,
                           const float* __restrict__ W1, const float* __restrict__ b1,
                           const float* __restrict__ W2, const float* __restrict__ b2,
                           const float* __restrict__ W3, const float* __restrict__ b3,
                           const float* __restrict__ cs) {
    const int b = threadIdx.x;
    if (b >= B_N) return;
    float s = 0.f;
    for (int i = 0; i < NCHUNK; ++i) s += g_partial[b * NCHUNK + i];

    float ci[1 + F_META];
    ci[0] = s / (float)T_LEN;
    for (int i = 0; i < F_META; ++i) ci[1 + i] = meta[b * F_META + i];

    float h1[32];
    for (int j = 0; j < 32; ++j) {
        float a = b1[j];
        for (int i = 0; i < 1 + F_META; ++i) a = fmaf(W1[j * (1 + F_META) + i], ci[i], a);
        h1[j] = fmaxf(a, 0.f);
    }
    float h2[16];
    for (int j = 0; j < 16; ++j) {
        float a = b2[j];
        for (int i = 0; i < 32; ++i) a = fmaf(W2[j * 32 + i], h1[i], a);
        h2[j] = fmaxf(a, 0.f);
    }
    float f = b3[0];
    for (int i = 0; i < 16; ++i) f = fmaf(W3[i], h2[i], f);
    g_scale[b] = 1.f + cs[0] * tanhf(f);
}

// ---------------------------------------------------------------------------
// K4: in-place rescale of the baseline by (1 + correction)
// ---------------------------------------------------------------------------
__global__ void scale_kernel(float* __restrict__ out) {
    int idx = blockIdx.x * blockDim.x + threadIdx.x;   // over B*T/4 float4s
    const int per_b = T_LEN / 4;
    int b = idx / per_b;
    float s = g_scale[b];
    float4* o4 = (float4*)out;
    float4 v = o4[idx];
    v.x *= s; v.y *= s; v.z *= s; v.w *= s;
    o4[idx] = v;
}

// ---------------------------------------------------------------------------
// Launch
// ---------------------------------------------------------------------------
extern "C" void kernel_launch(void* const* d_in, const int* in_sizes, int n_in,
                              void* d_out, int out_size) {
    const float* att  = (const float*)d_in[0];   // (B,1,T)
    const float* meta = (const float*)d_in[1];   // (B,8)
    const float* tw   = (const float*)d_in[2];   // (8640,)
    const float* W1   = (const float*)d_in[3];
    const float* b1   = (const float*)d_in[4];
    const float* W2   = (const float*)d_in[5];
    const float* b2   = (const float*)d_in[6];
    const float* W3   = (const float*)d_in[7];
    const float* b3   = (const float*)d_in[8];
    const float* cs   = (const float*)d_in[9];
    float* out = (float*)d_out;

    const int smem_bytes = (W_LEN + TILE + W_LEN) * (int)sizeof(float);  // 77312
    cudaFuncSetAttribute(conv_kernel, cudaFuncAttributeMaxDynamicSharedMemorySize, smem_bytes);

    softmax_flip_kernel<<<1, 256>>>(tw);
    pad_kernel<<<(B_N * XPAD_LEN + 255) / 256, 256>>>(att);
    conv_kernel<<<dim3(T_LEN / TILE, B_N), CTHREADS, smem_bytes>>>(out);
    reduce_kernel<<<dim3(NCHUNK, B_N), 256>>>(out);
    mlp_kernel<<<1, 32>>>(meta, W1, b1, W2, b2, W3, b3, cs);
    scale_kernel<<<(B_N * T_LEN / 4 + 255) / 256, 256>>>(out);
}

// round 8
// speedup vs baseline: 5.0616x; 2.9359x over previous
#include <cuda_runtime.h>
#include <cuda_bf16.h>
#include <cstdint>

// ---------------------------------------------------------------------------
// Problem constants
// ---------------------------------------------------------------------------
#define T_LEN   262144
#define B_N     16
#define W_LEN   8640
#define PAD     4320
#define F_META  8
#define NCHUNK  32

// GEMM decomposition
#define M_CTA   512            // output rows per CTA
#define GRID_G  (T_LEN / M_CTA) // 512 CTAs
#define NSTEP   576            // k16 steps (j up to 9215 >= 511+8639)
#define NCHK    9              // xs chunks of 1024
#define JT      1024           // j elems per chunk
#define XSROW   1032           // xs row pitch in elems (+8 pad -> conflict-free)
#define WBUF    9792           // guarded w buffer elems (512 + 8640 + 640)
#define WOFF    512
#define XPITCH  271872         // gxp row pitch elems (>= 261632 + 9216)

// smem byte offsets
#define WH_OFF   0
#define WL_OFF   19584
#define XSH_OFF  39168
#define XSL_OFF  72192
#define SMEM_SZ  105216

// ---------------------------------------------------------------------------
// Device scratch (no cudaMalloc allowed)
// ---------------------------------------------------------------------------
__device__ float g_w[W_LEN];
__device__ __align__(16) unsigned short g_wh[WBUF];
__device__ __align__(16) unsigned short g_wl[WBUF];
__device__ __align__(16) unsigned short gxph[B_N * XPITCH];   // 8.7 MB
__device__ __align__(16) unsigned short gxpl[B_N * XPITCH];
__device__ float g_partial[B_N * NCHUNK];
__device__ float g_scale[B_N];

// ---------------------------------------------------------------------------
// Helpers
// ---------------------------------------------------------------------------
__device__ __forceinline__ uint32_t pk(const unsigned short* p) {
    return (uint32_t)p[0] | ((uint32_t)p[1] << 16);
}
__device__ __forceinline__ void mma16816(float* d, uint32_t a0, uint32_t a1,
                                         uint32_t a2, uint32_t a3,
                                         uint32_t b0, uint32_t b1) {
    asm volatile(
        "mma.sync.aligned.m16n8k16.row.col.f32.bf16.bf16.f32 "
        "{%0,%1,%2,%3}, {%4,%5,%6,%7}, {%8,%9}, {%0,%1,%2,%3};"
        : "+f"(d[0]), "+f"(d[1]), "+f"(d[2]), "+f"(d[3])
        : "r"(a0), "r"(a1), "r"(a2), "r"(a3), "r"(b0), "r"(b1));
}

// ---------------------------------------------------------------------------
// Prep 1: softmax over temporal_weights, flipped -> g_w
// ---------------------------------------------------------------------------
__global__ void softmax_flip_kernel(const float* __restrict__ tw) {
    __shared__ float red[256];
    __shared__ float s_max, s_invsum;
    const int tid = threadIdx.x;

    float m = -1e30f;
    for (int i = tid; i < W_LEN; i += 256) m = fmaxf(m, tw[i]);
    red[tid] = m; __syncthreads();
    for (int s = 128; s > 0; s >>= 1) {
        if (tid < s) red[tid] = fmaxf(red[tid], red[tid + s]);
        __syncthreads();
    }
    if (tid == 0) s_max = red[0];
    __syncthreads();
    const float mx = s_max;
    __syncthreads();

    float sum = 0.f;
    for (int i = tid; i < W_LEN; i += 256) sum += expf(tw[i] - mx);
    red[tid] = sum; __syncthreads();
    for (int s = 128; s > 0; s >>= 1) {
        if (tid < s) red[tid] += red[tid + s];
        __syncthreads();
    }
    if (tid == 0) s_invsum = 1.f / red[0];
    __syncthreads();
    const float inv = s_invsum;

    for (int i = tid; i < W_LEN; i += 256)
        g_w[W_LEN - 1 - i] = expf(tw[i] - mx) * inv;
}

// ---------------------------------------------------------------------------
// Prep 2: guarded split-bf16 weight buffer
// ---------------------------------------------------------------------------
__global__ void wsplit_kernel() {
    for (int i = threadIdx.x; i < WBUF; i += 256) {
        int wi = i - WOFF;
        float v = (wi >= 0 && wi < W_LEN) ? g_w[wi] : 0.f;
        __nv_bfloat16 h = __float2bfloat16(v);
        float lo = v - __bfloat162float(h);
        __nv_bfloat16 l = __float2bfloat16(lo);
        g_wh[i] = __bfloat16_as_ushort(h);
        g_wl[i] = __bfloat16_as_ushort(l);
    }
}

// ---------------------------------------------------------------------------
// Prep 3: edge-padded split-bf16 input planes.  gxp[n][u] = att[n][clamp(u-PAD)]
// ---------------------------------------------------------------------------
__global__ void xsplit_kernel(const float* __restrict__ att) {
    long long idx = (long long)blockIdx.x * blockDim.x + threadIdx.x;
    if (idx >= (long long)B_N * XPITCH) return;
    int n = (int)(idx / XPITCH);
    int u = (int)(idx - (long long)n * XPITCH);
    int t = u - PAD;
    t = min(max(t, 0), T_LEN - 1);
    float v = att[n * T_LEN + t];
    __nv_bfloat16 h = __float2bfloat16(v);
    float lo = v - __bfloat162float(h);
    __nv_bfloat16 l = __float2bfloat16(lo);
    gxph[idx] = __bfloat16_as_ushort(h);
    gxpl[idx] = __bfloat16_as_ushort(l);
}

// ---------------------------------------------------------------------------
// Main GEMM: Toeplitz conv via mma.sync m16n8k16 bf16, split-bf16 3-pass.
// CTA = 256 thr / 8 warps; warp w owns rows [64w, 64w+64) of the CTA's 512.
// A-fragment ring depth 4 exploits frag(i,s) = frag(0,s-i); A3==A0 (Toeplitz).
// ---------------------------------------------------------------------------
__global__ void __launch_bounds__(256, 2) gemm_kernel(float* __restrict__ out) {
    extern __shared__ unsigned char smem[];
    unsigned short* wh  = (unsigned short*)(smem + WH_OFF);
    unsigned short* wl  = (unsigned short*)(smem + WL_OFF);
    unsigned short* xsh = (unsigned short*)(smem + XSH_OFF);
    unsigned short* xsl = (unsigned short*)(smem + XSL_OFF);

    const int tid  = threadIdx.x;
    const int warp = tid >> 5;
    const int lane = tid & 31;
    const int Wbase = warp * 64;
    const int r0 = lane >> 2;
    const int c0 = (lane & 3) * 2;
    const int t0 = blockIdx.x * M_CTA;

    // stage weights (38.3 KB) once
    for (int i = tid; i < WBUF / 8; i += 256) {
        ((uint4*)wh)[i] = ((const uint4*)g_wh)[i];
        ((uint4*)wl)[i] = ((const uint4*)g_wl)[i];
    }

    // per-thread B row pointers (n = lane/4 (+8), k0 = c0)
    const unsigned short* bh0 = xsh + (lane >> 2) * XSROW + c0;
    const unsigned short* bh1 = xsh + ((lane >> 2) + 8) * XSROW + c0;
    const unsigned short* bl0 = xsl + (lane >> 2) * XSROW + c0;
    const unsigned short* bl1 = xsl + ((lane >> 2) + 8) * XSROW + c0;

    float acc[4][2][4];
#pragma unroll
    for (int i = 0; i < 4; i++)
#pragma unroll
        for (int nb = 0; nb < 2; nb++)
#pragma unroll
            for (int q = 0; q < 4; q++) acc[i][nb][q] = 0.f;

    uint32_t Ah[4][3], Al[4][3];
#pragma unroll
    for (int i = 0; i < 4; i++)
#pragma unroll
        for (int q = 0; q < 3; q++) { Ah[i][q] = 0u; Al[i][q] = 0u; }

    for (int chunk = 0; chunk < NCHK; ++chunk) {
        __syncthreads();
        // stage xs chunk: 16 rows x 1024 elems, hi+lo planes (64 KB)
        {
            const int xbase = t0 + chunk * JT;
            for (int it = tid; it < 4096; it += 256) {
                int plane = it >> 11;
                int r = (it >> 7) & 15;
                int q = it & 127;
                const unsigned short* src =
                    (plane ? gxpl : gxph) + (size_t)r * XPITCH + xbase + q * 8;
                unsigned short* dst = (plane ? xsl : xsh) + r * XSROW + q * 8;
                *(uint4*)dst = *(const uint4*)src;
            }
        }
        __syncthreads();

        const int s0 = chunk * 64;
#pragma unroll 4
        for (int sl = 0; sl < 64; ++sl) {
            const int s = s0 + sl;
            const int slot = sl & 3;          // s ≡ sl (mod 4)
            // load fragBase(s): pairs at base, base-8, base+8 (A3 == A0)
            const int base = WOFF + 16 * s - Wbase + c0 - r0;
            Ah[slot][0] = pk(wh + base);
            Ah[slot][1] = pk(wh + base - 8);
            Ah[slot][2] = pk(wh + base + 8);
            Al[slot][0] = pk(wl + base);
            Al[slot][1] = pk(wl + base - 8);
            Al[slot][2] = pk(wl + base + 8);

            // B fragments for this k-step (jj local)
            const int jj = 16 * sl;
            uint32_t bh[2][2], bl[2][2];
            bh[0][0] = *(const uint32_t*)(bh0 + jj);
            bh[0][1] = *(const uint32_t*)(bh0 + jj + 8);
            bh[1][0] = *(const uint32_t*)(bh1 + jj);
            bh[1][1] = *(const uint32_t*)(bh1 + jj + 8);
            bl[0][0] = *(const uint32_t*)(bl0 + jj);
            bl[0][1] = *(const uint32_t*)(bl0 + jj + 8);
            bl[1][0] = *(const uint32_t*)(bl1 + jj);
            bl[1][1] = *(const uint32_t*)(bl1 + jj + 8);

#pragma unroll
            for (int ib = 0; ib < 4; ++ib) {
                const int sig = (sl - ib) & 3;
                const uint32_t h0 = Ah[sig][0], h1 = Ah[sig][1], h2 = Ah[sig][2];
                const uint32_t l0 = Al[sig][0], l1 = Al[sig][1], l2 = Al[sig][2];
#pragma unroll
                for (int nb = 0; nb < 2; ++nb) {
                    mma16816(acc[ib][nb], h0, h1, h2, h0, bh[nb][0], bh[nb][1]);
                    mma16816(acc[ib][nb], h0, h1, h2, h0, bl[nb][0], bl[nb][1]);
                    mma16816(acc[ib][nb], l0, l1, l2, l0, bh[nb][0], bh[nb][1]);
                }
            }
        }
    }

    // ---- epilogue: transpose through smem, coalesced store ----
    __syncthreads();
    float* smt = (float*)smem;               // [16][520]
#pragma unroll
    for (int ib = 0; ib < 4; ++ib) {
        const int mloc = Wbase + ib * 16 + r0;
#pragma unroll
        for (int nb = 0; nb < 2; ++nb) {
            const int n = c0 + nb * 8;
            smt[n * 520 + mloc]           = acc[ib][nb][0];
            smt[(n + 1) * 520 + mloc]     = acc[ib][nb][1];
            smt[n * 520 + mloc + 8]       = acc[ib][nb][2];
            smt[(n + 1) * 520 + mloc + 8] = acc[ib][nb][3];
        }
    }
    __syncthreads();
    for (int e = tid; e < B_N * M_CTA; e += 256) {
        int n = e >> 9;
        int mloc = e & 511;
        out[n * T_LEN + t0 + mloc] = smt[n * 520 + mloc];
    }
}

// ---------------------------------------------------------------------------
// Mean reduction, MLP, final scale
// ---------------------------------------------------------------------------
__global__ void reduce_kernel(const float* __restrict__ base) {
    __shared__ float red[256];
    const int b = blockIdx.y, c = blockIdx.x;
    const int chunk = T_LEN / NCHUNK;
    const float4* p = (const float4*)(base + b * T_LEN + c * chunk);
    float s = 0.f;
    for (int i = threadIdx.x; i < chunk / 4; i += 256) {
        float4 v = p[i];
        s += (v.x + v.y) + (v.z + v.w);
    }
    red[threadIdx.x] = s; __syncthreads();
    for (int st = 128; st > 0; st >>= 1) {
        if (threadIdx.x < st) red[threadIdx.x] += red[threadIdx.x + st];
        __syncthreads();
    }
    if (threadIdx.x == 0) g_partial[b * NCHUNK + c] = red[0];
}

__global__ void mlp_kernel(const float* __restrict__ meta,
                           const float* __restrict__ W1, const float* __restrict__ b1,
                           const float* __restrict__ W2, const float* __restrict__ b2,
                           const float* __restrict__ W3, const float* __restrict__ b3,
                           const float* __restrict__ cs) {
    const int b = threadIdx.x;
    if (b >= B_N) return;
    float s = 0.f;
    for (int i = 0; i < NCHUNK; ++i) s += g_partial[b * NCHUNK + i];

    float ci[1 + F_META];
    ci[0] = s / (float)T_LEN;
    for (int i = 0; i < F_META; ++i) ci[1 + i] = meta[b * F_META + i];

    float h1[32];
    for (int j = 0; j < 32; ++j) {
        float a = b1[j];
        for (int i = 0; i < 1 + F_META; ++i) a = fmaf(W1[j * (1 + F_META) + i], ci[i], a);
        h1[j] = fmaxf(a, 0.f);
    }
    float h2[16];
    for (int j = 0; j < 16; ++j) {
        float a = b2[j];
        for (int i = 0; i < 32; ++i) a = fmaf(W2[j * 32 + i], h1[i], a);
        h2[j] = fmaxf(a, 0.f);
    }
    float f = b3[0];
    for (int i = 0; i < 16; ++i) f = fmaf(W3[i], h2[i], f);
    g_scale[b] = 1.f + cs[0] * tanhf(f);
}

__global__ void scale_kernel(float* __restrict__ out) {
    int idx = blockIdx.x * blockDim.x + threadIdx.x;
    const int per_b = T_LEN / 4;
    int b = idx / per_b;
    float s = g_scale[b];
    float4* o4 = (float4*)out;
    float4 v = o4[idx];
    v.x *= s; v.y *= s; v.z *= s; v.w *= s;
    o4[idx] = v;
}

// ---------------------------------------------------------------------------
// Launch
// ---------------------------------------------------------------------------
extern "C" void kernel_launch(void* const* d_in, const int* in_sizes, int n_in,
                              void* d_out, int out_size) {
    const float* att  = (const float*)d_in[0];
    const float* meta = (const float*)d_in[1];
    const float* tw   = (const float*)d_in[2];
    const float* W1   = (const float*)d_in[3];
    const float* b1   = (const float*)d_in[4];
    const float* W2   = (const float*)d_in[5];
    const float* b2   = (const float*)d_in[6];
    const float* W3   = (const float*)d_in[7];
    const float* b3   = (const float*)d_in[8];
    const float* cs   = (const float*)d_in[9];
    float* out = (float*)d_out;

    cudaFuncSetAttribute(gemm_kernel, cudaFuncAttributeMaxDynamicSharedMemorySize, SMEM_SZ);

    softmax_flip_kernel<<<1, 256>>>(tw);
    wsplit_kernel<<<1, 256>>>();
    {
        long long tot = (long long)B_N * XPITCH;
        int blocks = (int)((tot + 255) / 256);
        xsplit_kernel<<<blocks, 256>>>(att);
    }
    gemm_kernel<<<GRID_G, 256, SMEM_SZ>>>(out);
    reduce_kernel<<<dim3(NCHUNK, B_N), 256>>>(out);
    mlp_kernel<<<1, 32>>>(meta, W1, b1, W2, b2, W3, b3, cs);
    scale_kernel<<<(B_N * T_LEN / 4 + 255) / 256, 256>>>(out);
}

// round 9
// speedup vs baseline: 5.3158x; 1.0502x over previous
#include <cuda_runtime.h>
#include <cuda_bf16.h>
#include <cstdint>

// ---------------------------------------------------------------------------
// Problem constants
// ---------------------------------------------------------------------------
#define T_LEN   262144
#define B_N     16
#define W_LEN   8640
#define PAD     4320
#define F_META  8
#define NCHUNK  32

// GEMM decomposition
#define M_CTA   512
#define GRID_G  (T_LEN / M_CTA)   // 512 CTAs
#define NCHK    9                 // x chunks of 1024 taps (64 k16-steps each)
#define JT      1024
#define XSROW   1040              // x smem pitch elems; 1040 % 64 == 16 -> conflict-free LDS.64
#define WBUF    9792              // guarded weight buffer elems
#define WOFF    512
#define XPITCH  271872            // gxp row pitch elems (mult of 16)

// smem byte offsets
#define WH_OFF   0
#define WL_OFF   19584
#define XSH_OFF  39168
#define XSL_OFF  72448
#define SMEM_SZ  105728

// ---------------------------------------------------------------------------
// Device scratch (no cudaMalloc allowed)
// ---------------------------------------------------------------------------
__device__ float g_w[W_LEN];
__device__ __align__(16) unsigned short g_wh[WBUF];
__device__ __align__(16) unsigned short g_wl[WBUF];
__device__ __align__(16) unsigned short gxph[B_N * XPITCH];   // 8.7 MB, frag-packed
__device__ __align__(16) unsigned short gxpl[B_N * XPITCH];
__device__ float g_partial[B_N * NCHUNK];
__device__ float g_scale[B_N];

// ---------------------------------------------------------------------------
// Helpers
// ---------------------------------------------------------------------------
__device__ __forceinline__ uint32_t pk(const unsigned short* p) {
    return (uint32_t)p[0] | ((uint32_t)p[1] << 16);
}
__device__ __forceinline__ void mma16816(float* d, uint32_t a0, uint32_t a1,
                                         uint32_t a2, uint32_t a3,
                                         uint32_t b0, uint32_t b1) {
    asm volatile(
        "mma.sync.aligned.m16n8k16.row.col.f32.bf16.bf16.f32 "
        "{%0,%1,%2,%3}, {%4,%5,%6,%7}, {%8,%9}, {%0,%1,%2,%3};"
        : "+f"(d[0]), "+f"(d[1]), "+f"(d[2]), "+f"(d[3])
        : "r"(a0), "r"(a1), "r"(a2), "r"(a3), "r"(b0), "r"(b1));
}

// ---------------------------------------------------------------------------
// Prep 1: softmax over temporal_weights, flipped -> g_w
// ---------------------------------------------------------------------------
__global__ void softmax_flip_kernel(const float* __restrict__ tw) {
    __shared__ float red[256];
    __shared__ float s_max, s_invsum;
    const int tid = threadIdx.x;

    float m = -1e30f;
    for (int i = tid; i < W_LEN; i += 256) m = fmaxf(m, tw[i]);
    red[tid] = m; __syncthreads();
    for (int s = 128; s > 0; s >>= 1) {
        if (tid < s) red[tid] = fmaxf(red[tid], red[tid + s]);
        __syncthreads();
    }
    if (tid == 0) s_max = red[0];
    __syncthreads();
    const float mx = s_max;
    __syncthreads();

    float sum = 0.f;
    for (int i = tid; i < W_LEN; i += 256) sum += expf(tw[i] - mx);
    red[tid] = sum; __syncthreads();
    for (int s = 128; s > 0; s >>= 1) {
        if (tid < s) red[tid] += red[tid + s];
        __syncthreads();
    }
    if (tid == 0) s_invsum = 1.f / red[0];
    __syncthreads();
    const float inv = s_invsum;

    for (int i = tid; i < W_LEN; i += 256)
        g_w[W_LEN - 1 - i] = expf(tw[i] - mx) * inv;
}

// ---------------------------------------------------------------------------
// Prep 2: guarded split-bf16 weight buffer
// ---------------------------------------------------------------------------
__global__ void wsplit_kernel() {
    for (int i = threadIdx.x; i < WBUF; i += 256) {
        int wi = i - WOFF;
        float v = (wi >= 0 && wi < W_LEN) ? g_w[wi] : 0.f;
        __nv_bfloat16 h = __float2bfloat16(v);
        float lo = v - __bfloat162float(h);
        __nv_bfloat16 l = __float2bfloat16(lo);
        g_wh[i] = __bfloat16_as_ushort(h);
        g_wl[i] = __bfloat16_as_ushort(l);
    }
}

// ---------------------------------------------------------------------------
// Prep 3: edge-padded split-bf16 input planes, FRAGMENT-PACKED.
// Within each aligned 16-elem group, elem k is stored at position
// perm(k) so that a thread's mma-B quad {c0,c0+1,c0+8,c0+9} is contiguous:
// order 0,1,8,9, 2,3,10,11, 4,5,12,13, 6,7,14,15.
// ---------------------------------------------------------------------------
__global__ void xsplit_kernel(const float* __restrict__ att) {
    long long idx = (long long)blockIdx.x * blockDim.x + threadIdx.x;
    if (idx >= (long long)B_N * XPITCH) return;
    int n = (int)(idx / XPITCH);
    int u = (int)(idx - (long long)n * XPITCH);
    int t = u - PAD;
    t = min(max(t, 0), T_LEN - 1);
    float v = att[n * T_LEN + t];
    __nv_bfloat16 h = __float2bfloat16(v);
    float lo = v - __bfloat162float(h);
    __nv_bfloat16 l = __float2bfloat16(lo);
    int g = u >> 4, p = u & 15;
    int np = (p < 8) ? (((p >> 1) << 2) | (p & 1))
                     : ((((p - 8) >> 1) << 2) | 2 | (p & 1));
    size_t dst = (size_t)n * XPITCH + (g << 4) + np;
    gxph[dst] = __bfloat16_as_ushort(h);
    gxpl[dst] = __bfloat16_as_ushort(l);
}

// ---------------------------------------------------------------------------
// Main GEMM: Toeplitz conv via mma.sync m16n8k16 bf16, split-bf16 3-pass.
// Per-warp band skip, A-fragment chaining, LDS.64 B loads, pass-major order.
// ---------------------------------------------------------------------------
__global__ void __launch_bounds__(256, 2) gemm_kernel(float* __restrict__ out) {
    extern __shared__ unsigned char smem[];
    unsigned short* wh  = (unsigned short*)(smem + WH_OFF);
    unsigned short* wl  = (unsigned short*)(smem + WL_OFF);
    unsigned short* xsh = (unsigned short*)(smem + XSH_OFF);
    unsigned short* xsl = (unsigned short*)(smem + XSL_OFF);

    const int tid  = threadIdx.x;
    const int warp = tid >> 5;
    const int lane = tid & 31;
    const int Wbase = warp * 64;
    const int r0 = lane >> 2;
    const int c0 = (lane & 3) * 2;
    const int t0 = blockIdx.x * M_CTA;
    const int smin = 4 * warp;          // frag(s)==0 outside [smin, smax]
    const int smax = 543 + 4 * warp;

    // stage weights (38.3 KB) once
    for (int i = tid; i < WBUF / 8; i += 256) {
        ((uint4*)wh)[i] = ((const uint4*)g_wh)[i];
        ((uint4*)wl)[i] = ((const uint4*)g_wl)[i];
    }

    // B pointers: quad {c0,c0+1,c0+8,c0+9} contiguous at elem offset 2*c0
    const unsigned short* bh0 = xsh + (lane >> 2) * XSROW + 2 * c0;
    const unsigned short* bh1 = xsh + ((lane >> 2) + 8) * XSROW + 2 * c0;
    const unsigned short* bl0 = xsl + (lane >> 2) * XSROW + 2 * c0;
    const unsigned short* bl1 = xsl + ((lane >> 2) + 8) * XSROW + 2 * c0;

    float acc[4][2][4];
#pragma unroll
    for (int i = 0; i < 4; i++)
#pragma unroll
        for (int nb = 0; nb < 2; nb++)
#pragma unroll
            for (int q = 0; q < 4; q++) acc[i][nb][q] = 0.f;

    uint32_t Ah[4][3], Al[4][3];
#pragma unroll
    for (int i = 0; i < 4; i++)
#pragma unroll
        for (int q = 0; q < 3; q++) { Ah[i][q] = 0u; Al[i][q] = 0u; }

    for (int chunk = 0; chunk < NCHK; ++chunk) {
        __syncthreads();
        // stage x chunk: 16 rows x 1024 elems x 2 planes (64 KB), bulk uint4
        {
            const int xbase = t0 + chunk * JT;
            for (int it = tid; it < 4096; it += 256) {
                int plane = it >> 11;
                int r = (it >> 7) & 15;
                int q = it & 127;
                const unsigned short* src =
                    (plane ? gxpl : gxph) + (size_t)r * XPITCH + xbase + q * 8;
                unsigned short* dst = (plane ? xsl : xsh) + r * XSROW + q * 8;
                *(uint4*)dst = *(const uint4*)src;
            }
        }
        __syncthreads();

        const int s0 = chunk * 64;
        int sl_lo = smin - s0; if (sl_lo < 0) sl_lo = 0;
        int sl_hi = smax - s0; if (sl_hi > 63) sl_hi = 63;
        if (sl_lo > sl_hi) continue;

        // chain preload: pA = pk(base(s_first) - 8)
        uint32_t pAh, pAl;
        {
            const int base0 = WOFF + 16 * (s0 + sl_lo) - Wbase + c0 - r0;
            pAh = pk(wh + base0 - 8);
            pAl = pk(wl + base0 - 8);
        }

#pragma unroll 4
        for (int sl = sl_lo; sl <= sl_hi; ++sl) {
            const int s = s0 + sl;
            const int slot = sl & 3;
            const int base = WOFF + 16 * s - Wbase + c0 - r0;
            // frag(s): [1] chained from previous step's [2]
            Ah[slot][1] = pAh;               Al[slot][1] = pAl;
            Ah[slot][0] = pk(wh + base);     Al[slot][0] = pk(wl + base);
            Ah[slot][2] = pk(wh + base + 8); Al[slot][2] = pk(wl + base + 8);
            pAh = Ah[slot][2];               pAl = Al[slot][2];

            // B fragments: one LDS.64 per (plane, nb)
            const int jj = 16 * sl;
            uint2 vh0 = *(const uint2*)(bh0 + jj);
            uint2 vh1 = *(const uint2*)(bh1 + jj);
            uint2 vl0 = *(const uint2*)(bl0 + jj);
            uint2 vl1 = *(const uint2*)(bl1 + jj);
            uint32_t bh[2][2] = {{vh0.x, vh0.y}, {vh1.x, vh1.y}};
            uint32_t bl[2][2] = {{vl0.x, vl0.y}, {vl1.x, vl1.y}};

            // pass-major: hh, hl, lh  (same-acc reuse distance = 8 mmas)
#pragma unroll
            for (int ib = 0; ib < 4; ++ib) {
                const int sig = (sl - ib) & 3;
                mma16816(acc[ib][0], Ah[sig][0], Ah[sig][1], Ah[sig][2], Ah[sig][0], bh[0][0], bh[0][1]);
                mma16816(acc[ib][1], Ah[sig][0], Ah[sig][1], Ah[sig][2], Ah[sig][0], bh[1][0], bh[1][1]);
            }
#pragma unroll
            for (int ib = 0; ib < 4; ++ib) {
                const int sig = (sl - ib) & 3;
                mma16816(acc[ib][0], Ah[sig][0], Ah[sig][1], Ah[sig][2], Ah[sig][0], bl[0][0], bl[0][1]);
                mma16816(acc[ib][1], Ah[sig][0], Ah[sig][1], Ah[sig][2], Ah[sig][0], bl[1][0], bl[1][1]);
            }
#pragma unroll
            for (int ib = 0; ib < 4; ++ib) {
                const int sig = (sl - ib) & 3;
                mma16816(acc[ib][0], Al[sig][0], Al[sig][1], Al[sig][2], Al[sig][0], bh[0][0], bh[0][1]);
                mma16816(acc[ib][1], Al[sig][0], Al[sig][1], Al[sig][2], Al[sig][0], bh[1][0], bh[1][1]);
            }
        }
    }

    // ---- epilogue: transpose through smem, coalesced store ----
    __syncthreads();
    float* smt = (float*)smem;               // [16][520]
#pragma unroll
    for (int ib = 0; ib < 4; ++ib) {
        const int mloc = Wbase + ib * 16 + r0;
#pragma unroll
        for (int nb = 0; nb < 2; ++nb) {
            const int n = c0 + nb * 8;
            smt[n * 520 + mloc]           = acc[ib][nb][0];
            smt[(n + 1) * 520 + mloc]     = acc[ib][nb][1];
            smt[n * 520 + mloc + 8]       = acc[ib][nb][2];
            smt[(n + 1) * 520 + mloc + 8] = acc[ib][nb][3];
        }
    }
    __syncthreads();
    for (int e = tid; e < B_N * M_CTA; e += 256) {
        int n = e >> 9;
        int mloc = e & 511;
        out[n * T_LEN + t0 + mloc] = smt[n * 520 + mloc];
    }
}

// ---------------------------------------------------------------------------
// Mean reduction, MLP, final scale
// ---------------------------------------------------------------------------
__global__ void reduce_kernel(const float* __restrict__ base) {
    __shared__ float red[256];
    const int b = blockIdx.y, c = blockIdx.x;
    const int chunk = T_LEN / NCHUNK;
    const float4* p = (const float4*)(base + b * T_LEN + c * chunk);
    float s = 0.f;
    for (int i = threadIdx.x; i < chunk / 4; i += 256) {
        float4 v = p[i];
        s += (v.x + v.y) + (v.z + v.w);
    }
    red[threadIdx.x] = s; __syncthreads();
    for (int st = 128; st > 0; st >>= 1) {
        if (threadIdx.x < st) red[threadIdx.x] += red[threadIdx.x + st];
        __syncthreads();
    }
    if (threadIdx.x == 0) g_partial[b * NCHUNK + c] = red[0];
}

__global__ void mlp_kernel(const float* __restrict__ meta,
                           const float* __restrict__ W1, const float* __restrict__ b1,
                           const float* __restrict__ W2, const float* __restrict__ b2,
                           const float* __restrict__ W3, const float* __restrict__ b3,
                           const float* __restrict__ cs) {
    const int b = threadIdx.x;
    if (b >= B_N) return;
    float s = 0.f;
    for (int i = 0; i < NCHUNK; ++i) s += g_partial[b * NCHUNK + i];

    float ci[1 + F_META];
    ci[0] = s / (float)T_LEN;
    for (int i = 0; i < F_META; ++i) ci[1 + i] = meta[b * F_META + i];

    float h1[32];
    for (int j = 0; j < 32; ++j) {
        float a = b1[j];
        for (int i = 0; i < 1 + F_META; ++i) a = fmaf(W1[j * (1 + F_META) + i], ci[i], a);
        h1[j] = fmaxf(a, 0.f);
    }
    float h2[16];
    for (int j = 0; j < 16; ++j) {
        float a = b2[j];
        for (int i = 0; i < 32; ++i) a = fmaf(W2[j * 32 + i], h1[i], a);
        h2[j] = fmaxf(a, 0.f);
    }
    float f = b3[0];
    for (int i = 0; i < 16; ++i) f = fmaf(W3[i], h2[i], f);
    g_scale[b] = 1.f + cs[0] * tanhf(f);
}

__global__ void scale_kernel(float* __restrict__ out) {
    int idx = blockIdx.x * blockDim.x + threadIdx.x;
    const int per_b = T_LEN / 4;
    int b = idx / per_b;
    float s = g_scale[b];
    float4* o4 = (float4*)out;
    float4 v = o4[idx];
    v.x *= s; v.y *= s; v.z *= s; v.w *= s;
    o4[idx] = v;
}

// ---------------------------------------------------------------------------
// Launch
// ---------------------------------------------------------------------------
extern "C" void kernel_launch(void* const* d_in, const int* in_sizes, int n_in,
                              void* d_out, int out_size) {
    const float* att  = (const float*)d_in[0];
    const float* meta = (const float*)d_in[1];
    const float* tw   = (const float*)d_in[2];
    const float* W1   = (const float*)d_in[3];
    const float* b1   = (const float*)d_in[4];
    const float* W2   = (const float*)d_in[5];
    const float* b2   = (const float*)d_in[6];
    const float* W3   = (const float*)d_in[7];
    const float* b3   = (const float*)d_in[8];
    const float* cs   = (const float*)d_in[9];
    float* out = (float*)d_out;

    cudaFuncSetAttribute(gemm_kernel, cudaFuncAttributeMaxDynamicSharedMemorySize, SMEM_SZ);

    softmax_flip_kernel<<<1, 256>>>(tw);
    wsplit_kernel<<<1, 256>>>();
    {
        long long tot = (long long)B_N * XPITCH;
        int blocks = (int)((tot + 255) / 256);
        xsplit_kernel<<<blocks, 256>>>(att);
    }
    gemm_kernel<<<GRID_G, 256, SMEM_SZ>>>(out);
    reduce_kernel<<<dim3(NCHUNK, B_N), 256>>>(out);
    mlp_kernel<<<1, 32>>>(meta, W1, b1, W2, b2, W3, b3, cs);
    scale_kernel<<<(B_N * T_LEN / 4 + 255) / 256, 256>>>(out);
}